// round 3
// baseline (speedup 1.0000x reference)
#include <cuda_runtime.h>

#define N_TOKENS 2048   // 8 * 256
#define DIM 128
#define DC 16
#define WARPS_PER_BLOCK 8
#define BLOCK_THREADS (WARPS_PER_BLOCK * 32)
#define GRID_BLOCKS (N_TOKENS / WARPS_PER_BLOCK)   // 256

__global__ void __launch_bounds__(BLOCK_THREADS) flf_quant_k3(
    const float* __restrict__ x,      // [2048, 128]
    const float* __restrict__ W_in,   // [128, 16]
    const float* __restrict__ b_in,   // [16]
    const float* __restrict__ W_out,  // [16, 128]
    const float* __restrict__ b_out,  // [128]
    float* __restrict__ out,          // [2048*128 (+ 2048 indices)]
    int write_indices)
{
    __shared__ float xs[WARPS_PER_BLOCK][DIM];

    const int warp = threadIdx.x >> 5;
    const int lane = threadIdx.x & 31;
    const int token = blockIdx.x * WARPS_PER_BLOCK + warp;
    const unsigned FULL = 0xFFFFFFFFu;

    const int q = lane >> 2;   // 0..7  : d-group
    const int m = lane & 3;    // 0..3  : e-block (e = 4m..4m+3)

    // ---- independent prefetches: x row (coalesced) + full W_out (coalesced, mask-independent) ----
    float4 xv = reinterpret_cast<const float4*>(x + (size_t)token * DIM)[lane];

    const float4* Wo4 = reinterpret_cast<const float4*>(W_out);   // [16][32] float4
    float4 wo[DC];
    #pragma unroll
    for (int e = 0; e < DC; e++) wo[e] = Wo4[e * (DIM / 4) + lane];

    float4 ob = reinterpret_cast<const float4*>(b_out)[lane];
    float4 bi = reinterpret_cast<const float4*>(b_in)[m];

    reinterpret_cast<float4*>(xs[warp])[lane] = xv;
    __syncwarp();

    // ---- z partials: lane accumulates z[4m..4m+3] over d = q + 8*it ----
    // W_in flat float4 chunk (lane + 32*it) == W_in[q+8*it, 4m..4m+3]  (coalesced + independent)
    const float4* Wi4 = reinterpret_cast<const float4*>(W_in);
    float4 z = make_float4(0.f, 0.f, 0.f, 0.f);
    #pragma unroll
    for (int it = 0; it < 16; it++) {
        float4 w = Wi4[lane + 32 * it];
        float xd = xs[warp][q + 8 * it];          // 4-way broadcast, conflict-free
        z.x = fmaf(xd, w.x, z.x);
        z.y = fmaf(xd, w.y, z.y);
        z.z = fmaf(xd, w.z, z.z);
        z.w = fmaf(xd, w.w, z.w);
    }

    // ---- butterfly reduce over q (xor 4, 8, 16): all lanes end with full z[4m..4m+3] ----
    #pragma unroll
    for (int off = 4; off <= 16; off <<= 1) {
        z.x += __shfl_xor_sync(FULL, z.x, off);
        z.y += __shfl_xor_sync(FULL, z.y, off);
        z.z += __shfl_xor_sync(FULL, z.z, off);
        z.w += __shfl_xor_sync(FULL, z.w, off);
    }
    z.x += bi.x; z.y += bi.y; z.z += bi.z; z.w += bi.w;

    // ---- signs -> 16-bit code. bit (15-e) = (z_e > 0); tie z==0 -> 0 (matches argmin) ----
    unsigned nib = ((unsigned)(z.x > 0.f) << 3) | ((unsigned)(z.y > 0.f) << 2)
                 | ((unsigned)(z.z > 0.f) << 1) |  (unsigned)(z.w > 0.f);
    unsigned mask = __reduce_or_sync(FULL, nib << (12 - 4 * m));   // == encoding index

    // ---- out = sum_e (+-1)*W_out[e,:] + b_out using prefetched wo[] ----
    #pragma unroll
    for (int e = 0; e < DC; e++) {
        const float s = ((mask >> (15 - e)) & 1u) ? 1.0f : -1.0f;
        ob.x = fmaf(s, wo[e].x, ob.x);
        ob.y = fmaf(s, wo[e].y, ob.y);
        ob.z = fmaf(s, wo[e].z, ob.z);
        ob.w = fmaf(s, wo[e].w, ob.w);
    }
    reinterpret_cast<float4*>(out + (size_t)token * DIM)[lane] = ob;

    if (write_indices && lane == 0) {
        out[(size_t)N_TOKENS * DIM + token] = (float)mask;
    }
}

extern "C" void kernel_launch(void* const* d_in, const int* in_sizes, int n_in,
                              void* d_out, int out_size)
{
    const float* x     = (const float*)d_in[0];
    const float* W_in  = (const float*)d_in[1];
    const float* b_in  = (const float*)d_in[2];
    const float* W_out = (const float*)d_in[3];
    const float* b_out = (const float*)d_in[4];
    float* out = (float*)d_out;

    int write_indices = (out_size >= N_TOKENS * DIM + N_TOKENS) ? 1 : 0;

    flf_quant_k3<<<GRID_BLOCKS, BLOCK_THREADS>>>(
        x, W_in, b_in, W_out, b_out, out, write_indices);
}

// round 5
// speedup vs baseline: 1.2788x; 1.2788x over previous
#include <cuda_runtime.h>

#define N_TOKENS 2048   // 8 * 256
#define DIM 128
#define DC 16

__global__ void __launch_bounds__(DIM) flf_quant_k4(
    const float* __restrict__ x,      // [2048, 128]
    const float* __restrict__ W_in,   // [128, 16]
    const float* __restrict__ b_in,   // [16]
    const float* __restrict__ W_out,  // [16, 128]
    const float* __restrict__ b_out,  // [128]
    float* __restrict__ out,          // [2048*128 (+ 2048 indices)]
    int write_indices)
{
    __shared__ float partial[DIM];

    const int token = blockIdx.x;
    const int t = threadIdx.x;
    const unsigned FULL = 0xFFFFFFFFu;

    // ---- coalesced x load: thread t holds x[t]; warp w holds x[32w .. 32w+31] ----
    float xv = x[(size_t)token * DIM + t];

    // ---- early, mask-independent prefetches (scalar -> ptxas keeps them live) ----
    float wo0  = W_out[ 0 * DIM + t], wo1  = W_out[ 1 * DIM + t];
    float wo2  = W_out[ 2 * DIM + t], wo3  = W_out[ 3 * DIM + t];
    float wo4  = W_out[ 4 * DIM + t], wo5  = W_out[ 5 * DIM + t];
    float wo6  = W_out[ 6 * DIM + t], wo7  = W_out[ 7 * DIM + t];
    float wo8  = W_out[ 8 * DIM + t], wo9  = W_out[ 9 * DIM + t];
    float wo10 = W_out[10 * DIM + t], wo11 = W_out[11 * DIM + t];
    float wo12 = W_out[12 * DIM + t], wo13 = W_out[13 * DIM + t];
    float wo14 = W_out[14 * DIM + t], wo15 = W_out[15 * DIM + t];
    float ob = b_out[t];

    // ---- z partial: e = t&15, chunk c = t>>4 (dims c*16 .. c*16+15).
    //      x[c*16+i] lives in this warp at lane ((c&1)<<4) + i  -> shfl, no smem ----
    const int e = t & 15;
    const int c = t >> 4;
    const int src_base = (c & 1) << 4;
    const float* wi = W_in + (size_t)(c * 16) * DC + e;

    float p = 0.0f;
    #pragma unroll
    for (int i = 0; i < 16; i++) {
        float xd = __shfl_sync(FULL, xv, src_base + i);
        p = fmaf(xd, wi[i * DC], p);
    }
    partial[t] = p;
    __syncthreads();

    // ---- every warp redundantly reduces z_e (e = lane&15; halves agree) ----
    float z = b_in[e];
    #pragma unroll
    for (int cc = 0; cc < 8; cc++) z += partial[cc * 16 + e];

    // bit e of mask = (z_e > 0); tie z==0 -> 0 (matches argmin lowest-index).
    unsigned mask = __ballot_sync(FULL, z > 0.0f) & 0xFFFFu;

    // ---- out dim t = b_out[t] + sum_e s_e * W_out[e,t] (prefetched) ----
    #define ACC(E, W) { float s = ((mask >> (E)) & 1u) ? 1.0f : -1.0f; ob = fmaf(s, (W), ob); }
    ACC(0,  wo0);  ACC(1,  wo1);  ACC(2,  wo2);  ACC(3,  wo3);
    ACC(4,  wo4);  ACC(5,  wo5);  ACC(6,  wo6);  ACC(7,  wo7);
    ACC(8,  wo8);  ACC(9,  wo9);  ACC(10, wo10); ACC(11, wo11);
    ACC(12, wo12); ACC(13, wo13); ACC(14, wo14); ACC(15, wo15);
    #undef ACC

    out[(size_t)token * DIM + t] = ob;

    if (write_indices && t == 0) {
        // encoding index: bit (15-e) of idx corresponds to dim e -> bit-reverse mask
        out[(size_t)N_TOKENS * DIM + token] = (float)(__brev(mask) >> 16);
    }
}

extern "C" void kernel_launch(void* const* d_in, const int* in_sizes, int n_in,
                              void* d_out, int out_size)
{
    const float* x     = (const float*)d_in[0];
    const float* W_in  = (const float*)d_in[1];
    const float* b_in  = (const float*)d_in[2];
    const float* W_out = (const float*)d_in[3];
    const float* b_out = (const float*)d_in[4];
    float* out = (float*)d_out;

    int write_indices = (out_size >= N_TOKENS * DIM + N_TOKENS) ? 1 : 0;

    flf_quant_k4<<<N_TOKENS, DIM>>>(x, W_in, b_in, W_out, b_out, out, write_indices);
}

// round 7
// speedup vs baseline: 1.3385x; 1.0467x over previous
#include <cuda_runtime.h>

#define N_TOKENS 2048   // 8 * 256
#define DIM 128
#define DC 16
#define TPB 2           // tokens per block
#define GRID_BLOCKS (N_TOKENS / TPB)   // 1024

__global__ void __launch_bounds__(DIM) flf_quant_k5(
    const float* __restrict__ x,      // [2048, 128]
    const float* __restrict__ W_in,   // [128, 16]
    const float* __restrict__ b_in,   // [16]
    const float* __restrict__ W_out,  // [16, 128]
    const float* __restrict__ b_out,  // [128]
    float* __restrict__ out,          // [2048*128 (+ 2048 indices)]
    int write_indices)
{
    __shared__ float partial0[DIM];
    __shared__ float partial1[DIM];

    const int token0 = blockIdx.x * TPB;
    const int t = threadIdx.x;
    const unsigned FULL = 0xFFFFFFFFu;

    // ---- coalesced x loads for both tokens: thread t holds x_g[t] ----
    const float* xb = x + (size_t)token0 * DIM;
    float xv0 = xb[t];
    float xv1 = xb[DIM + t];

    // ---- z partials: e = t&15, chunk c = t>>4 (dims c*16..c*16+15).
    //      x_g[c*16+i] lives in this warp at lane ((c&1)<<4)+i  -> shfl, no smem.
    //      W_in weights are shared between the two tokens. ----
    const int e = t & 15;
    const int c = t >> 4;
    const int src_base = (c & 1) << 4;
    const float* wi = W_in + (size_t)(c * 16) * DC + e;

    float p0 = 0.0f, p1 = 0.0f;
    #pragma unroll
    for (int i = 0; i < 16; i++) {
        float w = wi[i * DC];
        float xd0 = __shfl_sync(FULL, xv0, src_base + i);
        float xd1 = __shfl_sync(FULL, xv1, src_base + i);
        p0 = fmaf(xd0, w, p0);
        p1 = fmaf(xd1, w, p1);
    }
    partial0[t] = p0;
    partial1[t] = p1;

    // ---- mask-independent prefetches (scalar, shared by both tokens) ----
    float wo0  = W_out[ 0 * DIM + t], wo1  = W_out[ 1 * DIM + t];
    float wo2  = W_out[ 2 * DIM + t], wo3  = W_out[ 3 * DIM + t];
    float wo4  = W_out[ 4 * DIM + t], wo5  = W_out[ 5 * DIM + t];
    float wo6  = W_out[ 6 * DIM + t], wo7  = W_out[ 7 * DIM + t];
    float wo8  = W_out[ 8 * DIM + t], wo9  = W_out[ 9 * DIM + t];
    float wo10 = W_out[10 * DIM + t], wo11 = W_out[11 * DIM + t];
    float wo12 = W_out[12 * DIM + t], wo13 = W_out[13 * DIM + t];
    float wo14 = W_out[14 * DIM + t], wo15 = W_out[15 * DIM + t];
    float bo = b_out[t];
    float bi = b_in[e];

    __syncthreads();

    // ---- every warp redundantly reduces z_e for both tokens (e = lane&15) ----
    float z0 = bi, z1 = bi;
    #pragma unroll
    for (int cc = 0; cc < 8; cc++) {
        z0 += partial0[cc * 16 + e];
        z1 += partial1[cc * 16 + e];
    }

    // bit e = (z_e > 0); tie z==0 -> 0 (matches argmin lowest-index).
    unsigned mask0 = __ballot_sync(FULL, z0 > 0.0f) & 0xFFFFu;
    unsigned mask1 = __ballot_sync(FULL, z1 > 0.0f) & 0xFFFFu;

    // ---- out dim t for both tokens using shared prefetched W_out column ----
    float ob0 = bo, ob1 = bo;
    #define ACC(E, W) { \
        float s0 = ((mask0 >> (E)) & 1u) ? 1.0f : -1.0f; \
        float s1 = ((mask1 >> (E)) & 1u) ? 1.0f : -1.0f; \
        ob0 = fmaf(s0, (W), ob0); \
        ob1 = fmaf(s1, (W), ob1); }
    ACC(0,  wo0);  ACC(1,  wo1);  ACC(2,  wo2);  ACC(3,  wo3);
    ACC(4,  wo4);  ACC(5,  wo5);  ACC(6,  wo6);  ACC(7,  wo7);
    ACC(8,  wo8);  ACC(9,  wo9);  ACC(10, wo10); ACC(11, wo11);
    ACC(12, wo12); ACC(13, wo13); ACC(14, wo14); ACC(15, wo15);
    #undef ACC

    float* ob = out + (size_t)token0 * DIM;
    ob[t] = ob0;
    ob[DIM + t] = ob1;

    if (write_indices && t == 0) {
        out[(size_t)N_TOKENS * DIM + token0]     = (float)(__brev(mask0) >> 16);
        out[(size_t)N_TOKENS * DIM + token0 + 1] = (float)(__brev(mask1) >> 16);
    }
}

extern "C" void kernel_launch(void* const* d_in, const int* in_sizes, int n_in,
                              void* d_out, int out_size)
{
    const float* x     = (const float*)d_in[0];
    const float* W_in  = (const float*)d_in[1];
    const float* b_in  = (const float*)d_in[2];
    const float* W_out = (const float*)d_in[3];
    const float* b_out = (const float*)d_in[4];
    float* out = (float*)d_out;

    int write_indices = (out_size >= N_TOKENS * DIM + N_TOKENS) ? 1 : 0;

    flf_quant_k5<<<GRID_BLOCKS, DIM>>>(x, W_in, b_in, W_out, b_out, out, write_indices);
}

// round 8
// speedup vs baseline: 1.5154x; 1.1322x over previous
#include <cuda_runtime.h>

#define N_TOKENS 2048   // 8 * 256
#define DIM 128
#define DC 16
#define TPB 2           // tokens per block
#define GRID_BLOCKS (N_TOKENS / TPB)   // 1024

__global__ void __launch_bounds__(DIM) flf_quant_k6(
    const float* __restrict__ x,      // [2048, 128]
    const float* __restrict__ W_in,   // [128, 16]
    const float* __restrict__ b_in,   // [16]
    const float* __restrict__ W_out,  // [16, 128]
    const float* __restrict__ b_out,  // [128]
    float* __restrict__ out,          // [2048*128 (+ 2048 indices)]
    int write_indices)
{
    // [warp][token][ep] float2 -> flat floats: idx = (w*2+tok)*16 + e
    __shared__ float2 sm[4][TPB][8];

    const int token0 = blockIdx.x * TPB;
    const int t = threadIdx.x;
    const int lane = t & 31;
    const int warp = t >> 5;
    const unsigned FULL = 0xFFFFFFFFu;

    const int ep  = t & 7;           // e-pair index: covers e = 2*ep, 2*ep+1
    const int cpl = (t >> 3) & 3;    // dim-chunk within warp (8 dims each)

    // ---- coalesced x loads: thread t holds x_g[t] (dims of warp w: [32w,32w+32)) ----
    const float* xb = x + (size_t)token0 * DIM;
    float xv0 = xb[t];
    float xv1 = xb[DIM + t];

    // ---- W_in as float2: quad idx = d*8 + ep, d = warp*32 + cpl*8 + i  (8 LDG.64) ----
    const float2* Wi2 = reinterpret_cast<const float2*>(W_in);
    const int dbase = warp * 32 + cpl * 8;
    float2 wi[8];
    #pragma unroll
    for (int i = 0; i < 8; i++) wi[i] = Wi2[(dbase + i) * (DC / 2) + ep];

    // ---- mask-independent W_out / bias prefetch (shared by both tokens) ----
    float wo[DC];
    #pragma unroll
    for (int e = 0; e < DC; e++) wo[e] = W_out[e * DIM + t];
    float bo = b_out[t];

    // ---- z partials: 8 broadcasts/token feed float2 FMAs (4 fma per broadcast pair) ----
    float2 p0 = make_float2(0.f, 0.f), p1 = make_float2(0.f, 0.f);
    #pragma unroll
    for (int i = 0; i < 8; i++) {
        float xd0 = __shfl_sync(FULL, xv0, cpl * 8 + i);
        float xd1 = __shfl_sync(FULL, xv1, cpl * 8 + i);
        p0.x = fmaf(xd0, wi[i].x, p0.x);
        p0.y = fmaf(xd0, wi[i].y, p0.y);
        p1.x = fmaf(xd1, wi[i].x, p1.x);
        p1.y = fmaf(xd1, wi[i].y, p1.y);
    }

    // ---- warp pre-reduce over the 4 chunks (xor 8, then 16) ----
    p0.x += __shfl_xor_sync(FULL, p0.x, 8);
    p0.y += __shfl_xor_sync(FULL, p0.y, 8);
    p1.x += __shfl_xor_sync(FULL, p1.x, 8);
    p1.y += __shfl_xor_sync(FULL, p1.y, 8);
    p0.x += __shfl_xor_sync(FULL, p0.x, 16);
    p0.y += __shfl_xor_sync(FULL, p0.y, 16);
    p1.x += __shfl_xor_sync(FULL, p1.x, 16);
    p1.y += __shfl_xor_sync(FULL, p1.y, 16);

    if (lane < 8) {
        sm[warp][0][ep] = p0;
        sm[warp][1][ep] = p1;
    }
    __syncthreads();

    // ---- final reduce: lane's e = lane&15; smf[(w*2+tok)*16 + e], conflict-free ----
    const int e = lane & 15;
    const float* smf = reinterpret_cast<const float*>(sm);
    const float bi = b_in[e];
    float z0 = ((smf[ 0 + e] + smf[32 + e]) + (smf[64 + e] + smf[ 96 + e])) + bi;
    float z1 = ((smf[16 + e] + smf[48 + e]) + (smf[80 + e] + smf[112 + e])) + bi;

    // bit e = (z_e > 0); tie z==0 -> 0 (matches argmin lowest-index).
    unsigned mask0 = __ballot_sync(FULL, z0 > 0.0f) & 0xFFFFu;
    unsigned mask1 = __ballot_sync(FULL, z1 > 0.0f) & 0xFFFFu;

    // ---- out dim t for both tokens; two independent accumulator chains each ----
    float a0 = bo, c0 = 0.f, a1 = bo, c1 = 0.f;
    #define ACC(E, A0, C0, A1, C1) { \
        float s0 = ((mask0 >> (E)) & 1u) ? 1.0f : -1.0f; \
        float s1 = ((mask1 >> (E)) & 1u) ? 1.0f : -1.0f; \
        A0 = fmaf(s0, wo[E], A0); \
        A1 = fmaf(s1, wo[E], A1); }
    ACC(0,  a0, c0, a1, c1); ACC(1,  c0, a0, c1, a1);
    ACC(2,  a0, c0, a1, c1); ACC(3,  c0, a0, c1, a1);
    ACC(4,  a0, c0, a1, c1); ACC(5,  c0, a0, c1, a1);
    ACC(6,  a0, c0, a1, c1); ACC(7,  c0, a0, c1, a1);
    ACC(8,  a0, c0, a1, c1); ACC(9,  c0, a0, c1, a1);
    ACC(10, a0, c0, a1, c1); ACC(11, c0, a0, c1, a1);
    ACC(12, a0, c0, a1, c1); ACC(13, c0, a0, c1, a1);
    ACC(14, a0, c0, a1, c1); ACC(15, c0, a0, c1, a1);
    #undef ACC

    float* op = out + (size_t)token0 * DIM;
    op[t]       = a0 + c0;
    op[DIM + t] = a1 + c1;

    if (write_indices && t == 0) {
        out[(size_t)N_TOKENS * DIM + token0]     = (float)(__brev(mask0) >> 16);
        out[(size_t)N_TOKENS * DIM + token0 + 1] = (float)(__brev(mask1) >> 16);
    }
}

extern "C" void kernel_launch(void* const* d_in, const int* in_sizes, int n_in,
                              void* d_out, int out_size)
{
    const float* x     = (const float*)d_in[0];
    const float* W_in  = (const float*)d_in[1];
    const float* b_in  = (const float*)d_in[2];
    const float* W_out = (const float*)d_in[3];
    const float* b_out = (const float*)d_in[4];
    float* out = (float*)d_out;

    int write_indices = (out_size >= N_TOKENS * DIM + N_TOKENS) ? 1 : 0;

    flf_quant_k6<<<GRID_BLOCKS, DIM>>>(x, W_in, b_in, W_out, b_out, out, write_indices);
}

// round 9
// speedup vs baseline: 1.6618x; 1.0966x over previous
#include <cuda_runtime.h>

#define N_TOKENS 2048   // 8 * 256
#define DIM 128
#define DC 16
#define TPB 2           // tokens per block
#define GRID_BLOCKS (N_TOKENS / TPB)   // 1024

__global__ void __launch_bounds__(DIM) flf_quant_k8(
    const float* __restrict__ x,      // [2048, 128]
    const float* __restrict__ W_in,   // [128, 16]
    const float* __restrict__ b_in,   // [16]
    const float* __restrict__ W_out,  // [16, 128]
    const float* __restrict__ b_out,  // [128]
    float* __restrict__ out,          // [2048*128 (+ 2048 indices)]
    int write_indices)
{
    // floats laid out as [warp][token][e]: offset = warp*32 + tok*16 + e
    __shared__ float2 sm[4][TPB][8];

    const int token0 = blockIdx.x * TPB;
    const int t = threadIdx.x;
    const int lane = t & 31;
    const int warp = t >> 5;
    const unsigned FULL = 0xFFFFFFFFu;

    const int ep  = t & 7;           // e-pair: covers e = 2*ep, 2*ep+1
    const int cpl = (t >> 3) & 3;    // 8-dim chunk within the warp's 32 dims
    const int dbase = warp * 32 + cpl * 8;

    // ---- direct x loads: the 8 dims this thread needs, both tokens (4x LDG.128,
    //      8 threads/chunk share addresses -> L1 broadcast) ----
    const float4* xq = reinterpret_cast<const float4*>(x + (size_t)token0 * DIM);
    const int qb = dbase >> 2;
    float4 xa0 = xq[qb],      xb0 = xq[qb + 1];        // token0
    float4 xa1 = xq[32 + qb], xb1 = xq[32 + qb + 1];   // token1

    // ---- W_in as float2: W_in[d][2ep..2ep+1], d = dbase..dbase+7 ----
    const float2* Wi2 = reinterpret_cast<const float2*>(W_in);
    float2 wi[8];
    #pragma unroll
    for (int i = 0; i < 8; i++) wi[i] = Wi2[(dbase + i) * (DC / 2) + ep];

    // ---- mask-independent W_out / bias prefetch (shared by both tokens) ----
    float wo[DC];
    #pragma unroll
    for (int e = 0; e < DC; e++) wo[e] = W_out[e * DIM + t];
    float bo = b_out[t];

    // ---- z partials: 8 dims x 2 e's x 2 tokens = 32 FMAs ----
    float2 p0 = make_float2(0.f, 0.f), p1 = make_float2(0.f, 0.f);
    #define STEP(XV0, XV1, I) \
        p0.x = fmaf((XV0), wi[I].x, p0.x); p0.y = fmaf((XV0), wi[I].y, p0.y); \
        p1.x = fmaf((XV1), wi[I].x, p1.x); p1.y = fmaf((XV1), wi[I].y, p1.y);
    STEP(xa0.x, xa1.x, 0) STEP(xa0.y, xa1.y, 1)
    STEP(xa0.z, xa1.z, 2) STEP(xa0.w, xa1.w, 3)
    STEP(xb0.x, xb1.x, 4) STEP(xb0.y, xb1.y, 5)
    STEP(xb0.z, xb1.z, 6) STEP(xb0.w, xb1.w, 7)
    #undef STEP

    // ---- warp pre-reduce over the 4 chunks (xor 8, then 16): 8 shfls ----
    p0.x += __shfl_xor_sync(FULL, p0.x, 8);
    p0.y += __shfl_xor_sync(FULL, p0.y, 8);
    p1.x += __shfl_xor_sync(FULL, p1.x, 8);
    p1.y += __shfl_xor_sync(FULL, p1.y, 8);
    p0.x += __shfl_xor_sync(FULL, p0.x, 16);
    p0.y += __shfl_xor_sync(FULL, p0.y, 16);
    p1.x += __shfl_xor_sync(FULL, p1.x, 16);
    p1.y += __shfl_xor_sync(FULL, p1.y, 16);

    if (lane < 8) {
        sm[warp][0][ep] = p0;
        sm[warp][1][ep] = p1;
    }
    __syncthreads();

    // ---- split-half final reduce: lane l handles token l>>4, dim l&15.
    //      offset collapses to smf[w*32 + lane] -> uniform, conflict-free ----
    const float* smf = reinterpret_cast<const float*>(sm);
    float z = ((smf[lane] + smf[32 + lane]) + (smf[64 + lane] + smf[96 + lane]))
            + b_in[lane & 15];

    // one ballot gives both masks; bit e = (z_e > 0); tie z==0 -> 0 (argmin lowest idx)
    unsigned b = __ballot_sync(FULL, z > 0.0f);
    unsigned mask0 = b & 0xFFFFu;
    unsigned mask1 = b >> 16;

    // ---- out dim t for both tokens; two accumulator chains per token ----
    float a0 = bo, c0 = 0.f, a1 = bo, c1 = 0.f;
    #define ACC(E, A0, A1) { \
        float s0 = (mask0 & (1u << (E))) ? 1.0f : -1.0f; \
        float s1 = (mask1 & (1u << (E))) ? 1.0f : -1.0f; \
        A0 = fmaf(s0, wo[E], A0); \
        A1 = fmaf(s1, wo[E], A1); }
    ACC(0,  a0, a1); ACC(1,  c0, c1);
    ACC(2,  a0, a1); ACC(3,  c0, c1);
    ACC(4,  a0, a1); ACC(5,  c0, c1);
    ACC(6,  a0, a1); ACC(7,  c0, c1);
    ACC(8,  a0, a1); ACC(9,  c0, c1);
    ACC(10, a0, a1); ACC(11, c0, c1);
    ACC(12, a0, a1); ACC(13, c0, c1);
    ACC(14, a0, a1); ACC(15, c0, c1);
    #undef ACC

    float* op = out + (size_t)token0 * DIM;
    op[t]       = a0 + c0;
    op[DIM + t] = a1 + c1;

    if (write_indices && t == 0) {
        out[(size_t)N_TOKENS * DIM + token0]     = (float)(__brev(mask0) >> 16);
        out[(size_t)N_TOKENS * DIM + token0 + 1] = (float)(__brev(mask1) >> 16);
    }
}

extern "C" void kernel_launch(void* const* d_in, const int* in_sizes, int n_in,
                              void* d_out, int out_size)
{
    const float* x     = (const float*)d_in[0];
    const float* W_in  = (const float*)d_in[1];
    const float* b_in  = (const float*)d_in[2];
    const float* W_out = (const float*)d_in[3];
    const float* b_out = (const float*)d_in[4];
    float* out = (float*)d_out;

    int write_indices = (out_size >= N_TOKENS * DIM + N_TOKENS) ? 1 : 0;

    flf_quant_k8<<<GRID_BLOCKS, DIM>>>(x, W_in, b_in, W_out, b_out, out, write_indices);
}